// round 9
// baseline (speedup 1.0000x reference)
#include <cuda_runtime.h>
#include <math.h>

#define BATCH 64
#define EMB   512
#define HID   512
#define G3    1536         // 3*HID
#define VOCAB 10000
#define TSRC  128
#define TDEC  127          // trg[:, :-1]

// persistent GRU kernel geometry
#define NBLK  128          // blocks (<= SM count, all co-resident)
#define CPB   4            // h-columns per block (128*4 = 512)
#define KCH   64           // k-chunk staged per double-buffer slot (= flag granularity)
#define NKCH  (HID / KCH)  // 8
#define SW_ROW 516         // padded row (floats) for weight smem (2064B, 16B aligned)
#define SH_ROW 68          // padded row (floats) for h smem (272B, 16B aligned)
#define SW_FLOATS (3 * CPB * SW_ROW)          // 6192
#define SH_FLOATS (2 * BATCH * SH_ROW)        // 8704
#define GRU_SMEM  ((SW_FLOATS + SH_FLOATS) * 4)  // 59584 bytes

// ---------------- scratch (device globals; no allocation allowed) ----------
__device__ float g_X [(size_t)BATCH * TSRC * EMB];   // embedded inputs
__device__ float g_GI[(size_t)BATCH * TSRC * G3];    // input projections (all t)
__device__ float g_Y [(size_t)BATCH * TSRC * HID];   // layer outputs
__device__ float g_H [4 * BATCH * HID];              // ping-pong hidden (2 layers x 2)
__device__ unsigned int g_FLAG[4][8];                // per-layer, per-chunk step counters

// ---------------- f32x2 packed-FMA helpers ----------------------------------
__device__ __forceinline__ void fma2(unsigned long long& d,
                                     unsigned long long a, unsigned long long b)
{
    asm("fma.rn.f32x2 %0, %1, %2, %0;" : "+l"(d) : "l"(a), "l"(b));
}
__device__ __forceinline__ float sum2(unsigned long long p)
{
    float lo, hi;
    asm("mov.b64 {%0, %1}, %2;" : "=f"(lo), "=f"(hi) : "l"(p));
    return lo + hi;
}
__device__ __forceinline__ unsigned long long dup2(float a)
{
    unsigned long long r;
    asm("mov.b64 %0, {%1, %1};" : "=l"(r) : "f"(a));
    return r;
}

// ---------------- init: zero out[t=0] slice + hidden + flags ----------------
__global__ void init_k(float* __restrict__ out)
{
    int i = blockIdx.x * blockDim.x + threadIdx.x;
    if (i < BATCH * VOCAB) {
        int b = i / VOCAB, v = i % VOCAB;
        out[((size_t)b * TSRC) * VOCAB + v] = 0.0f;
    }
    if (i < 4 * BATCH * HID) g_H[i] = 0.0f;
    if (i < 32) (&g_FLAG[0][0])[i] = 0u;
}

// ---------------- embedding gather (float4) ---------------------------------
__global__ void embed_k(const int* __restrict__ idx, const float* __restrict__ emb,
                        float* __restrict__ X, int T)
{
    int i = blockIdx.x * blockDim.x + threadIdx.x;
    int total = BATCH * T * (EMB / 4);
    if (i >= total) return;
    int e4 = i % (EMB / 4);
    int bt = i / (EMB / 4);
    int t  = bt % T;
    int b  = bt / T;
    int tok = idx[b * TSRC + t];               // idx rows have stride TSRC (128)
    reinterpret_cast<float4*>(X)[(size_t)bt * (EMB / 4) + e4] =
        reinterpret_cast<const float4*>(emb)[(size_t)tok * (EMB / 4) + e4];
}

// ---------------- generic tiled GEMM: C = A[M,K] @ W[N,K]^T + bias ----------
// mode 0: C[m*N + n]
// mode 1: FC scatter: m -> (b = m/TDEC, t = m%TDEC), C[((b*TSRC)+t+1)*VOCAB + n]
// Inner product uses fma.rn.f32x2: 8 packed FMAs (16 scalar) per k per thread.
#define GTM 64
#define GTN 64
#define GTK 16
__global__ __launch_bounds__(256) void gemm_bias(
    const float* __restrict__ A, const float* __restrict__ W,
    const float* __restrict__ bias, float* __restrict__ C,
    int M, int N, int K, int mode)
{
    __shared__ __align__(16) float sA[GTK][GTM];
    __shared__ __align__(16) float sB[GTK][GTN];
    int m0 = blockIdx.x * GTM;
    int n0 = blockIdx.y * GTN;
    int tid = threadIdx.x;
    int tx = tid & 15;          // n micro index
    int ty = tid >> 4;          // m micro index
    int lm = tid >> 2;          // 0..63 (row for staging)
    int lk = (tid & 3) * 4;     // 0,4,8,12

    unsigned long long acc2[4][2];
#pragma unroll
    for (int i = 0; i < 4; i++) { acc2[i][0] = 0ull; acc2[i][1] = 0ull; }

    for (int k0 = 0; k0 < K; k0 += GTK) {
        float4 av = *reinterpret_cast<const float4*>(&A[(size_t)(m0 + lm) * K + k0 + lk]);
        float4 bv = make_float4(0.f, 0.f, 0.f, 0.f);
        int wn = n0 + lm;
        if (wn < N)
            bv = *reinterpret_cast<const float4*>(&W[(size_t)wn * K + k0 + lk]);
        __syncthreads();
        sA[lk + 0][lm] = av.x; sA[lk + 1][lm] = av.y;
        sA[lk + 2][lm] = av.z; sA[lk + 3][lm] = av.w;
        sB[lk + 0][lm] = bv.x; sB[lk + 1][lm] = bv.y;
        sB[lk + 2][lm] = bv.z; sB[lk + 3][lm] = bv.w;
        __syncthreads();
#pragma unroll
        for (int k = 0; k < GTK; k++) {
            float a[4];
            *reinterpret_cast<float4*>(a) = *reinterpret_cast<const float4*>(&sA[k][ty * 4]);
            ulonglong2 bp = *reinterpret_cast<const ulonglong2*>(&sB[k][tx * 4]);
#pragma unroll
            for (int i = 0; i < 4; i++) {
                unsigned long long ad = dup2(a[i]);
                fma2(acc2[i][0], ad, bp.x);
                fma2(acc2[i][1], ad, bp.y);
            }
        }
    }

#pragma unroll
    for (int i = 0; i < 4; i++) {
        int m = m0 + ty * 4 + i;
        size_t rowbase;
        if (mode == 0) {
            rowbase = (size_t)m * N;
        } else {
            int b = m / TDEC, t = m % TDEC;
            rowbase = ((size_t)b * TSRC + t + 1) * VOCAB;
        }
        float accf[4];
        asm("mov.b64 {%0, %1}, %2;" : "=f"(accf[0]), "=f"(accf[1]) : "l"(acc2[i][0]));
        asm("mov.b64 {%0, %1}, %2;" : "=f"(accf[2]), "=f"(accf[3]) : "l"(acc2[i][1]));
#pragma unroll
        for (int j = 0; j < 4; j++) {
            int n = n0 + tx * 4 + j;
            if (n < N) {
                C[rowbase + n] = accf[j] + bias[n];
            }
        }
    }
}

// ---------------- helpers for persistent GRU --------------------------------
__device__ __forceinline__ void cp_async16(void* smem_dst, const void* gmem_src)
{
    unsigned int saddr = (unsigned int)__cvta_generic_to_shared(smem_dst);
    asm volatile("cp.async.cg.shared.global [%0], [%1], 16;\n"
                 :: "r"(saddr), "l"(gmem_src) : "memory");
}

// lane-0-per-warp acquire-poll on a chunk flag (with backoff); lanes sync after.
__device__ __forceinline__ void wait_flag(const unsigned int* p, unsigned int tgt)
{
    if ((threadIdx.x & 31) == 0) {
        unsigned int v;
        asm volatile("ld.acquire.gpu.global.u32 %0, [%1];" : "=r"(v) : "l"(p));
        while (v < tgt) {
            __nanosleep(64);
            asm volatile("ld.acquire.gpu.global.u32 %0, [%1];" : "=r"(v) : "l"(p));
        }
    }
    __syncwarp();
}

// ---------------- persistent GRU layer: all T steps in one launch -----------
// Block owns CPB=4 columns (one k-chunk). Per step, h streamed through smem in
// 8 double-buffered cp.async chunks; readiness tracked with 8 monotonic flags
// (16 producer blocks each). No global barrier: a block writes h only after it
// staged all 8 chunks (implicit rendezvous), so ping-pong is race-free.
__global__ __launch_bounds__(256, 1) void gru_layer(
    const float* __restrict__ Whh, const float* __restrict__ bhh,
    const float* __restrict__ GI, int T,
    float* __restrict__ hbuf0, float* __restrict__ hbuf1,
    float* __restrict__ Yout, int layer)
{
    extern __shared__ float smem[];
    float* sW = smem;                 // [3][CPB][SW_ROW]
    float* sH = smem + SW_FLOATS;     // [2][BATCH][SH_ROW]

    const int tid = threadIdx.x;
    const int bid = blockIdx.x;
    const int c0  = bid * CPB;
    const int c   = tid & 3;          // column within block
    const int b   = tid >> 2;         // batch 0..63
    const int cg  = c0 + c;           // global h column
    const int qh  = c0 >> 6;          // k-chunk containing column cg (for h_prev)
    unsigned int* myflag = &g_FLAG[layer][bid >> 4];
    const unsigned int* flags = &g_FLAG[layer][0];

    // ---- load this block's Whh slice into smem (once per layer) ----
    for (int idx = tid; idx < 3 * CPB * (HID / 4); idx += 256) {
        int r  = idx >> 7;            // 0..11 (HID/4 = 128 float4 per row)
        int k4 = idx & 127;
        int g  = r >> 2;
        int cc = r & 3;
        float4 v = reinterpret_cast<const float4*>(Whh)
                      [(size_t)(g * HID + c0 + cc) * (HID / 4) + k4];
        *(reinterpret_cast<float4*>(sW + (g * CPB + cc) * SW_ROW) + k4) = v;
    }
    const float br = bhh[cg];
    const float bz = bhh[HID + cg];
    const float bn = bhh[2 * HID + cg];
    __syncthreads();

    const ulonglong2* w2r = reinterpret_cast<const ulonglong2*>(sW + (0 * CPB + c) * SW_ROW);
    const ulonglong2* w2z = reinterpret_cast<const ulonglong2*>(sW + (1 * CPB + c) * SW_ROW);
    const ulonglong2* w2n = reinterpret_cast<const ulonglong2*>(sW + (2 * CPB + c) * SW_ROW);

    for (int t = 0; t < T; t++) {
        const float* hin  = (t & 1) ? hbuf1 : hbuf0;
        float*       hout = (t & 1) ? hbuf0 : hbuf1;
        const unsigned int tgt = 16u * (unsigned int)t;

        // GI loads are h-independent: issue early, consumed at epilogue.
        const size_t gib = ((size_t)b * T + t) * G3;
        const float ir  = GI[gib + cg];
        const float iz  = GI[gib + HID + cg];
        const float inn = GI[gib + 2 * HID + cg];

        // stage chunk 0
        if (t > 0) wait_flag(&flags[0], tgt);
        for (int i = tid; i < BATCH * (KCH / 4); i += 256) {
            int bb = i >> 4, k4 = i & 15;
            cp_async16(sH + bb * SH_ROW + k4 * 4, hin + bb * HID + k4 * 4);
        }
        asm volatile("cp.async.commit_group;\n" ::: "memory");

        unsigned long long ar0 = 0ull, ar1 = 0ull;
        unsigned long long az0 = 0ull, az1 = 0ull;
        unsigned long long an0 = 0ull, an1 = 0ull;
        float hprev = 0.f;

        for (int q = 0; q < NKCH; q++) {
            if (q + 1 < NKCH) {
                if (t > 0) wait_flag(&flags[q + 1], tgt);
                float* dst = sH + ((q + 1) & 1) * BATCH * SH_ROW;
                const float* src = hin + (q + 1) * KCH;
                for (int i = tid; i < BATCH * (KCH / 4); i += 256) {
                    int bb = i >> 4, k4 = i & 15;
                    cp_async16(dst + bb * SH_ROW + k4 * 4, src + bb * HID + k4 * 4);
                }
                asm volatile("cp.async.commit_group;\n" ::: "memory");
                asm volatile("cp.async.wait_group 1;\n" ::: "memory");
            } else {
                asm volatile("cp.async.wait_group 0;\n" ::: "memory");
            }
            __syncthreads();

            const ulonglong2* h2 = reinterpret_cast<const ulonglong2*>(
                sH + (q & 1) * BATCH * SH_ROW + b * SH_ROW);
            const int kb4 = q * (KCH / 4);
#pragma unroll
            for (int k4 = 0; k4 < KCH / 4; k4++) {
                ulonglong2 hp = h2[k4];
                ulonglong2 w;
                w = w2r[kb4 + k4]; fma2(ar0, w.x, hp.x); fma2(ar1, w.y, hp.y);
                w = w2z[kb4 + k4]; fma2(az0, w.x, hp.x); fma2(az1, w.y, hp.y);
                w = w2n[kb4 + k4]; fma2(an0, w.x, hp.x); fma2(an1, w.y, hp.y);
            }
            if (q == qh)
                hprev = sH[(q & 1) * BATCH * SH_ROW + b * SH_ROW + (cg & (KCH - 1))];
            __syncthreads();
        }

        // ---- fused gate epilogue (deterministic, per-thread) ----
        float gr = sum2(ar0) + sum2(ar1);
        float gz = sum2(az0) + sum2(az1);
        float gn = sum2(an0) + sum2(an1);
        float r = 1.0f / (1.0f + expf(-(ir + gr + br)));
        float z = 1.0f / (1.0f + expf(-(iz + gz + bz)));
        float n = tanhf(inn + r * (gn + bn));
        float hv = (1.0f - z) * n + z * hprev;
        hout[b * HID + cg] = hv;
        Yout[((size_t)b * T + t) * HID + cg] = hv;

        // release this block's chunk for step t+1
        __threadfence();
        __syncthreads();
        if (tid == 0) atomicAdd(myflag, 1u);
    }
}

// ---------------- launch -----------------------------------------------------
extern "C" void kernel_launch(void* const* d_in, const int* in_sizes, int n_in,
                              void* d_out, int out_size)
{
    const int*   src     = (const int*)  d_in[0];
    const int*   trg     = (const int*)  d_in[1];
    const float* enc_emb = (const float*)d_in[2];
    const float* enc_Wih = (const float*)d_in[3];
    const float* enc_Whh = (const float*)d_in[4];
    const float* enc_bih = (const float*)d_in[5];
    const float* enc_bhh = (const float*)d_in[6];
    const float* dec_emb = (const float*)d_in[7];
    const float* dec_Wih = (const float*)d_in[8];
    const float* dec_Whh = (const float*)d_in[9];
    const float* dec_bih = (const float*)d_in[10];
    const float* dec_bhh = (const float*)d_in[11];
    const float* fc_W    = (const float*)d_in[12];
    const float* fc_b    = (const float*)d_in[13];
    float* out = (float*)d_out;

    float *X, *GI, *Y, *H;
    cudaGetSymbolAddress((void**)&X,  g_X);
    cudaGetSymbolAddress((void**)&GI, g_GI);
    cudaGetSymbolAddress((void**)&Y,  g_Y);
    cudaGetSymbolAddress((void**)&H,  g_H);

    cudaFuncSetAttribute(gru_layer, cudaFuncAttributeMaxDynamicSharedMemorySize,
                         GRU_SMEM);

    // zero t=0 output slice + initial hidden states + flags
    init_k<<<(BATCH * VOCAB + 255) / 256, 256>>>(out);

    // ===================== encoder =====================
    embed_k<<<(BATCH * TSRC * (EMB / 4) + 255) / 256, 256>>>(src, enc_emb, X, TSRC);
    for (int l = 0; l < 2; l++) {
        const float* Ain = (l == 0) ? X : Y;
        gemm_bias<<<dim3((BATCH * TSRC) / GTM, G3 / GTN), 256>>>(
            Ain, enc_Wih + (size_t)l * G3 * HID, enc_bih + l * G3,
            GI, BATCH * TSRC, G3, (l == 0) ? EMB : HID, 0);
        float* h0 = H + (2 * l + 0) * BATCH * HID;
        float* h1 = H + (2 * l + 1) * BATCH * HID;
        // T=128 (even): final hidden ends in h0 — exactly where decoder reads it.
        gru_layer<<<NBLK, 256, GRU_SMEM>>>(
            enc_Whh + (size_t)l * G3 * HID, enc_bhh + l * G3, GI, TSRC, h0, h1, Y, l);
    }

    // ===================== decoder =====================
    embed_k<<<(BATCH * TDEC * (EMB / 4) + 255) / 256, 256>>>(trg, dec_emb, X, TDEC);
    for (int l = 0; l < 2; l++) {
        const float* Ain = (l == 0) ? X : Y;
        gemm_bias<<<dim3((BATCH * TDEC) / GTM, G3 / GTN), 256>>>(
            Ain, dec_Wih + (size_t)l * G3 * HID, dec_bih + l * G3,
            GI, BATCH * TDEC, G3, (l == 0) ? EMB : HID, 0);
        float* h0 = H + (2 * l + 0) * BATCH * HID;   // holds encoder final hidden
        float* h1 = H + (2 * l + 1) * BATCH * HID;
        gru_layer<<<NBLK, 256, GRU_SMEM>>>(
            dec_Whh + (size_t)l * G3 * HID, dec_bhh + l * G3, GI, TDEC, h0, h1, Y, 2 + l);
    }

    // ===================== FC head =====================
    gemm_bias<<<dim3((BATCH * TDEC) / GTM, (VOCAB + GTN - 1) / GTN), 256>>>(
        Y, fc_W, fc_b, out, BATCH * TDEC, VOCAB, HID, 1);
}

// round 10
// speedup vs baseline: 1.0564x; 1.0564x over previous
#include <cuda_runtime.h>
#include <math.h>

#define BATCH 64
#define EMB   512
#define HID   512
#define G3    1536         // 3*HID
#define VOCAB 10000
#define TSRC  128
#define TDEC  127          // trg[:, :-1]

// persistent GRU geometry: 128 blocks x 256 threads, 1 block/SM
#define NBLK  128
#define NTHR  256
#define CPB   4            // columns per block
#define SHROW 516          // h row stride in floats (129 x 16B, odd -> conflict-free)
#define SWROW 516          // w row stride in floats
#define SW_FLOATS (12 * SWROW)        // 3 gates x 4 cols
#define SH_FLOATS (BATCH * SHROW)     // 33024
#define SP_FLOATS (768 * 12)          // partials: 768 outputs x (8 warps + pad)
#define GRU_SMEM ((SW_FLOATS + SH_FLOATS + SP_FLOATS) * 4)   // 193728 B

// ---------------- scratch (device globals; no allocation allowed) ----------
__device__ float g_X [(size_t)BATCH * TSRC * EMB];   // embedded inputs
__device__ float g_GI[(size_t)BATCH * TSRC * G3];    // input proj, layout [t][n][b]
__device__ float g_Y [(size_t)BATCH * TSRC * HID];   // layer outputs
__device__ float g_H [4 * BATCH * HID];              // ping-pong hidden (2 layers x 2)
__device__ unsigned int g_FLAG[4][8];                // per-layer, per-chunk step counters

// ---------------- f32x2 packed-FMA helpers ----------------------------------
__device__ __forceinline__ void fma2(unsigned long long& d,
                                     unsigned long long a, unsigned long long b)
{
    asm("fma.rn.f32x2 %0, %1, %2, %0;" : "+l"(d) : "l"(a), "l"(b));
}
__device__ __forceinline__ float sum2(unsigned long long p)
{
    float lo, hi;
    asm("mov.b64 {%0, %1}, %2;" : "=f"(lo), "=f"(hi) : "l"(p));
    return lo + hi;
}
__device__ __forceinline__ unsigned long long dup2(float a)
{
    unsigned long long r;
    asm("mov.b64 %0, {%1, %1};" : "=l"(r) : "f"(a));
    return r;
}

// ---------------- init: zero out[t=0] slice + hidden + flags ----------------
__global__ void init_k(float* __restrict__ out)
{
    int i = blockIdx.x * blockDim.x + threadIdx.x;
    if (i < BATCH * VOCAB) {
        int b = i / VOCAB, v = i % VOCAB;
        out[((size_t)b * TSRC) * VOCAB + v] = 0.0f;
    }
    if (i < 4 * BATCH * HID) g_H[i] = 0.0f;
    if (i < 32) (&g_FLAG[0][0])[i] = 0u;
}

// ---------------- embedding gather (float4) ---------------------------------
__global__ void embed_k(const int* __restrict__ idx, const float* __restrict__ emb,
                        float* __restrict__ X, int T)
{
    int i = blockIdx.x * blockDim.x + threadIdx.x;
    int total = BATCH * T * (EMB / 4);
    if (i >= total) return;
    int e4 = i % (EMB / 4);
    int bt = i / (EMB / 4);
    int t  = bt % T;
    int b  = bt / T;
    int tok = idx[b * TSRC + t];               // idx rows have stride TSRC (128)
    reinterpret_cast<float4*>(X)[(size_t)bt * (EMB / 4) + e4] =
        reinterpret_cast<const float4*>(emb)[(size_t)tok * (EMB / 4) + e4];
}

// ---------------- generic tiled GEMM: C = A[M,K] @ W[N,K]^T + bias ----------
// mode 0: C[m*N + n]
// mode 1: FC scatter: m -> (b,t), C[((b*TSRC)+t+1)*VOCAB + n]
// mode 2: GI transpose-scatter: m=(b,t), C[(t*G3 + n)*64 + b]  (b-contiguous)
#define GTM 64
#define GTN 64
#define GTK 16
__global__ __launch_bounds__(256) void gemm_bias(
    const float* __restrict__ A, const float* __restrict__ W,
    const float* __restrict__ bias, float* __restrict__ C,
    int M, int N, int K, int mode, int Tdim)
{
    __shared__ __align__(16) float sA[GTK][GTM];
    __shared__ __align__(16) float sB[GTK][GTN];
    int m0 = blockIdx.x * GTM;
    int n0 = blockIdx.y * GTN;
    int tid = threadIdx.x;
    int tx = tid & 15;          // n micro index
    int ty = tid >> 4;          // m micro index
    int lm = tid >> 2;          // 0..63 (row for staging)
    int lk = (tid & 3) * 4;     // 0,4,8,12

    unsigned long long acc2[4][2];
#pragma unroll
    for (int i = 0; i < 4; i++) { acc2[i][0] = 0ull; acc2[i][1] = 0ull; }

    for (int k0 = 0; k0 < K; k0 += GTK) {
        float4 av = *reinterpret_cast<const float4*>(&A[(size_t)(m0 + lm) * K + k0 + lk]);
        float4 bv = make_float4(0.f, 0.f, 0.f, 0.f);
        int wn = n0 + lm;
        if (wn < N)
            bv = *reinterpret_cast<const float4*>(&W[(size_t)wn * K + k0 + lk]);
        __syncthreads();
        sA[lk + 0][lm] = av.x; sA[lk + 1][lm] = av.y;
        sA[lk + 2][lm] = av.z; sA[lk + 3][lm] = av.w;
        sB[lk + 0][lm] = bv.x; sB[lk + 1][lm] = bv.y;
        sB[lk + 2][lm] = bv.z; sB[lk + 3][lm] = bv.w;
        __syncthreads();
#pragma unroll
        for (int k = 0; k < GTK; k++) {
            float a[4];
            *reinterpret_cast<float4*>(a) = *reinterpret_cast<const float4*>(&sA[k][ty * 4]);
            ulonglong2 bp = *reinterpret_cast<const ulonglong2*>(&sB[k][tx * 4]);
#pragma unroll
            for (int i = 0; i < 4; i++) {
                unsigned long long ad = dup2(a[i]);
                fma2(acc2[i][0], ad, bp.x);
                fma2(acc2[i][1], ad, bp.y);
            }
        }
    }

#pragma unroll
    for (int i = 0; i < 4; i++) {
        int m = m0 + ty * 4 + i;
        float accf[4];
        asm("mov.b64 {%0, %1}, %2;" : "=f"(accf[0]), "=f"(accf[1]) : "l"(acc2[i][0]));
        asm("mov.b64 {%0, %1}, %2;" : "=f"(accf[2]), "=f"(accf[3]) : "l"(acc2[i][1]));
        if (mode == 0) {
            size_t rowbase = (size_t)m * N;
#pragma unroll
            for (int j = 0; j < 4; j++) {
                int n = n0 + tx * 4 + j;
                if (n < N) C[rowbase + n] = accf[j] + bias[n];
            }
        } else if (mode == 1) {
            int b = m / TDEC, t = m % TDEC;
            size_t rowbase = ((size_t)b * TSRC + t + 1) * VOCAB;
#pragma unroll
            for (int j = 0; j < 4; j++) {
                int n = n0 + tx * 4 + j;
                if (n < N) C[rowbase + n] = accf[j] + bias[n];
            }
        } else {
            int b = m / Tdim, t = m % Tdim;
#pragma unroll
            for (int j = 0; j < 4; j++) {
                int n = n0 + tx * 4 + j;
                C[((size_t)t * G3 + n) * 64 + b] = accf[j] + bias[n];
            }
        }
    }
}

// ---------------- helpers for persistent GRU --------------------------------
__device__ __forceinline__ void cp_async16(void* smem_dst, const void* gmem_src)
{
    unsigned int saddr = (unsigned int)__cvta_generic_to_shared(smem_dst);
    asm volatile("cp.async.cg.shared.global [%0], [%1], 16;\n"
                 :: "r"(saddr), "l"(gmem_src) : "memory");
}

// lane-0 acquire-poll on a chunk flag (with small backoff); warp syncs after.
__device__ __forceinline__ void wait_flag(const unsigned int* p, unsigned int tgt)
{
    if ((threadIdx.x & 31) == 0) {
        unsigned int v;
        asm volatile("ld.acquire.gpu.global.u32 %0, [%1];" : "=r"(v) : "l"(p));
        while (v < tgt) {
            __nanosleep(32);
            asm volatile("ld.acquire.gpu.global.u32 %0, [%1];" : "=r"(v) : "l"(p));
        }
    }
    __syncwarp();
}

// ---------------- persistent GRU layer ---------------------------------------
// Block: 4 columns x 64 batches. Warp w: k-slice [64w, 64w+64); lane = batch
// (2 per thread). w-loads broadcast (1 cyc), h-loads conflict-free (SHROW=516).
// 8-way k-split reduced via smem partials, then fused gate epilogue.
__global__ __launch_bounds__(NTHR, 1) void gru_layer(
    const float* __restrict__ Whh, const float* __restrict__ bhh,
    const float* __restrict__ GI, int T,
    float* __restrict__ hbuf0, float* __restrict__ hbuf1,
    float* __restrict__ Yout, int layer)
{
    extern __shared__ float smem[];
    float* sW = smem;                       // [12][SWROW]
    float* sH = smem + SW_FLOATS;           // [64][SHROW]
    float* sP = sH + SH_FLOATS;             // [768][12]

    const int tid = threadIdx.x;
    const int w   = tid >> 5;               // warp 0..7 = k-slice
    const int l   = tid & 31;               // lane = batch (and batch+32)
    const int bid = blockIdx.x;
    const int c0  = bid * CPB;

    // epilogue role: thread handles (cc, be)
    const int cc  = tid >> 6;               // 0..3
    const int be  = tid & 63;               // 0..63
    const int cg  = c0 + cc;

    unsigned int* myflag = &g_FLAG[layer][bid >> 4];
    const unsigned int* flags = &g_FLAG[layer][0];

    // ---- load Whh slice (12 rows x 512) to smem, once per layer ----
    for (int idx = tid; idx < 12 * (HID / 4); idx += NTHR) {
        int r  = idx >> 7;                  // row = g*4+cc2
        int k4 = idx & 127;
        float4 v = reinterpret_cast<const float4*>(Whh)
                       [(size_t)((r >> 2) * HID + c0 + (r & 3)) * (HID / 4) + k4];
        *reinterpret_cast<float4*>(sW + r * SWROW + k4 * 4) = v;
    }
    const float br = bhh[cg];
    const float bz = bhh[HID + cg];
    const float bn = bhh[2 * HID + cg];
    __syncthreads();

    const float* sWb  = sW + 64 * w;        // this warp's k-slice within w rows
    float* sHr0 = sH + l * SHROW + 64 * w;
    float* sHr1 = sH + (l + 32) * SHROW + 64 * w;

    for (int t = 0; t < T; t++) {
        const float* hin  = (t & 1) ? hbuf1 : hbuf0;
        float*       hout = (t & 1) ? hbuf0 : hbuf1;
        const unsigned int tgt = 16u * (unsigned int)t;

        // ---- per-warp: wait for this k-chunk's producers, stage 16KB ----
        if (t > 0) wait_flag(&flags[w], tgt);
        {
            const float* s0 = hin + l * HID + 64 * w;
            const float* s1 = hin + (l + 32) * HID + 64 * w;
#pragma unroll
            for (int j = 0; j < 16; j++) cp_async16(sHr0 + 4 * j, s0 + 4 * j);
#pragma unroll
            for (int j = 0; j < 16; j++) cp_async16(sHr1 + 4 * j, s1 + 4 * j);
        }
        asm volatile("cp.async.commit_group;\n" ::: "memory");

        // GI loads (coalesced, [t][n][b] layout) — issue early
        const size_t gt = (size_t)t * G3;
        const float ir  = GI[(gt + cg) * 64 + be];
        const float iz  = GI[(gt + HID + cg) * 64 + be];
        const float inn = GI[(gt + 2 * HID + cg) * 64 + be];

        asm volatile("cp.async.wait_group 0;\n" ::: "memory");

        // ---- k-loop over this warp's 64-k slice ----
        unsigned long long acc[12][2];
#pragma unroll
        for (int r = 0; r < 12; r++) { acc[r][0] = 0ull; acc[r][1] = 0ull; }

#pragma unroll 4
        for (int kq = 0; kq < 16; kq++) {
            ulonglong2 H0 = *reinterpret_cast<const ulonglong2*>(sHr0 + 4 * kq);
            ulonglong2 H1 = *reinterpret_cast<const ulonglong2*>(sHr1 + 4 * kq);
#pragma unroll
            for (int r = 0; r < 12; r++) {
                ulonglong2 Wv = *reinterpret_cast<const ulonglong2*>(
                    sWb + r * SWROW + 4 * kq);
                fma2(acc[r][0], Wv.x, H0.x);
                fma2(acc[r][0], Wv.y, H0.y);
                fma2(acc[r][1], Wv.x, H1.x);
                fma2(acc[r][1], Wv.y, H1.y);
            }
        }

        // ---- fold + store partials ----
#pragma unroll
        for (int r = 0; r < 12; r++) {
            sP[(r * 64 + l) * 12 + w]      = sum2(acc[r][0]);
            sP[(r * 64 + l + 32) * 12 + w] = sum2(acc[r][1]);
        }
        __syncthreads();

        // ---- combine (deterministic order) + fused gate epilogue ----
        float gsum[3];
#pragma unroll
        for (int g = 0; g < 3; g++) {
            int o = (g * 4 + cc) * 64 + be;
            float4 pa = *reinterpret_cast<const float4*>(sP + o * 12);
            float4 pb = *reinterpret_cast<const float4*>(sP + o * 12 + 4);
            gsum[g] = ((pa.x + pa.y) + (pa.z + pa.w)) +
                      ((pb.x + pb.y) + (pb.z + pb.w));
        }
        float hprev = sH[be * SHROW + cg];
        float r = 1.0f / (1.0f + expf(-(ir + gsum[0] + br)));
        float z = 1.0f / (1.0f + expf(-(iz + gsum[1] + bz)));
        float n = tanhf(inn + r * (gsum[2] + bn));
        float hv = (1.0f - z) * n + z * hprev;
        hout[be * HID + cg] = hv;
        Yout[((size_t)be * T + t) * HID + cg] = hv;

        // ---- release this block's chunk for step t+1 ----
        __threadfence();
        __syncthreads();
        if (tid == 0) atomicAdd(myflag, 1u);
    }
}

// ---------------- launch -----------------------------------------------------
extern "C" void kernel_launch(void* const* d_in, const int* in_sizes, int n_in,
                              void* d_out, int out_size)
{
    const int*   src     = (const int*)  d_in[0];
    const int*   trg     = (const int*)  d_in[1];
    const float* enc_emb = (const float*)d_in[2];
    const float* enc_Wih = (const float*)d_in[3];
    const float* enc_Whh = (const float*)d_in[4];
    const float* enc_bih = (const float*)d_in[5];
    const float* enc_bhh = (const float*)d_in[6];
    const float* dec_emb = (const float*)d_in[7];
    const float* dec_Wih = (const float*)d_in[8];
    const float* dec_Whh = (const float*)d_in[9];
    const float* dec_bih = (const float*)d_in[10];
    const float* dec_bhh = (const float*)d_in[11];
    const float* fc_W    = (const float*)d_in[12];
    const float* fc_b    = (const float*)d_in[13];
    float* out = (float*)d_out;

    float *X, *GI, *Y, *H;
    cudaGetSymbolAddress((void**)&X,  g_X);
    cudaGetSymbolAddress((void**)&GI, g_GI);
    cudaGetSymbolAddress((void**)&Y,  g_Y);
    cudaGetSymbolAddress((void**)&H,  g_H);

    cudaFuncSetAttribute(gru_layer, cudaFuncAttributeMaxDynamicSharedMemorySize,
                         GRU_SMEM);

    // zero t=0 output slice + initial hidden states + flags
    init_k<<<(BATCH * VOCAB + 255) / 256, 256>>>(out);

    // ===================== encoder =====================
    embed_k<<<(BATCH * TSRC * (EMB / 4) + 255) / 256, 256>>>(src, enc_emb, X, TSRC);
    for (int l = 0; l < 2; l++) {
        const float* Ain = (l == 0) ? X : Y;
        gemm_bias<<<dim3((BATCH * TSRC) / GTM, G3 / GTN), 256>>>(
            Ain, enc_Wih + (size_t)l * G3 * HID, enc_bih + l * G3,
            GI, BATCH * TSRC, G3, (l == 0) ? EMB : HID, 2, TSRC);
        float* h0 = H + (2 * l + 0) * BATCH * HID;
        float* h1 = H + (2 * l + 1) * BATCH * HID;
        // T=128 (even): final hidden lands in h0 — exactly where decoder reads it.
        gru_layer<<<NBLK, NTHR, GRU_SMEM>>>(
            enc_Whh + (size_t)l * G3 * HID, enc_bhh + l * G3, GI, TSRC, h0, h1, Y, l);
    }

    // ===================== decoder =====================
    embed_k<<<(BATCH * TDEC * (EMB / 4) + 255) / 256, 256>>>(trg, dec_emb, X, TDEC);
    for (int l = 0; l < 2; l++) {
        const float* Ain = (l == 0) ? X : Y;
        gemm_bias<<<dim3((BATCH * TDEC) / GTM, G3 / GTN), 256>>>(
            Ain, dec_Wih + (size_t)l * G3 * HID, dec_bih + l * G3,
            GI, BATCH * TDEC, G3, (l == 0) ? EMB : HID, 2, TDEC);
        float* h0 = H + (2 * l + 0) * BATCH * HID;   // encoder final hidden
        float* h1 = H + (2 * l + 1) * BATCH * HID;
        gru_layer<<<NBLK, NTHR, GRU_SMEM>>>(
            dec_Whh + (size_t)l * G3 * HID, dec_bhh + l * G3, GI, TDEC, h0, h1, Y, 2 + l);
    }

    // ===================== FC head =====================
    gemm_bias<<<dim3((BATCH * TDEC) / GTM, (VOCAB + GTN - 1) / GTN), 256>>>(
        Y, fc_W, fc_b, out, BATCH * TDEC, VOCAB, HID, 1, TDEC);
}

// round 12
// speedup vs baseline: 1.0738x; 1.0165x over previous
#include <cuda_runtime.h>
#include <math.h>

#define BATCH 64
#define EMB   512
#define HID   512
#define G3    1536         // 3*HID
#define VOCAB 10000
#define TSRC  128
#define TDEC  127          // trg[:, :-1]

// persistent GRU geometry: 128 blocks x 256 threads, 1 block/SM
#define NBLK  128
#define NTHR  256
#define CPB   4            // columns per block
#define SHROW 516          // h row stride in floats (odd x 4 -> conflict-free)
#define SWROW 516          // w row stride in floats
#define SW_FLOATS (12 * SWROW)        // 3 gates x 4 cols
#define SH_FLOATS (BATCH * SHROW)     // 33024
#define SP_FLOATS (768 * 12)          // partials: 768 outputs x (8 warps + pad)
#define SO_FLOATS (BATCH * 4 + 16)    // staged h/y outputs (64 batches x 4 cols)
#define GRU_SMEM ((SW_FLOATS + SH_FLOATS + SP_FLOATS + SO_FLOATS) * 4)

// ---------------- scratch (device globals; no allocation allowed) ----------
__device__ float g_X [(size_t)BATCH * TSRC * EMB];   // embedded inputs
__device__ float g_GI[(size_t)BATCH * TSRC * G3];    // input proj, layout [t][n][b]
__device__ float g_Y [(size_t)BATCH * TSRC * HID];   // layer outputs
__device__ float g_H [4 * BATCH * HID];              // ping-pong hidden (2 layers x 2)
__device__ unsigned int g_FLAG[4][8];                // per-layer, per-chunk step counters

// ---------------- f32x2 packed-FMA helpers ----------------------------------
__device__ __forceinline__ void fma2(unsigned long long& d,
                                     unsigned long long a, unsigned long long b)
{
    asm("fma.rn.f32x2 %0, %1, %2, %0;" : "+l"(d) : "l"(a), "l"(b));
}
__device__ __forceinline__ float sum2(unsigned long long p)
{
    float lo, hi;
    asm("mov.b64 {%0, %1}, %2;" : "=f"(lo), "=f"(hi) : "l"(p));
    return lo + hi;
}
__device__ __forceinline__ unsigned long long dup2(float a)
{
    unsigned long long r;
    asm("mov.b64 %0, {%1, %1};" : "=l"(r) : "f"(a));
    return r;
}

// ---------------- init: zero out[t=0] slice + hidden + flags ----------------
__global__ void init_k(float* __restrict__ out)
{
    int i = blockIdx.x * blockDim.x + threadIdx.x;
    if (i < BATCH * VOCAB) {
        int b = i / VOCAB, v = i % VOCAB;
        out[((size_t)b * TSRC) * VOCAB + v] = 0.0f;
    }
    if (i < 4 * BATCH * HID) g_H[i] = 0.0f;
    if (i < 32) (&g_FLAG[0][0])[i] = 0u;
}

// ---------------- embedding gather (float4) ---------------------------------
__global__ void embed_k(const int* __restrict__ idx, const float* __restrict__ emb,
                        float* __restrict__ X, int T)
{
    int i = blockIdx.x * blockDim.x + threadIdx.x;
    int total = BATCH * T * (EMB / 4);
    if (i >= total) return;
    int e4 = i % (EMB / 4);
    int bt = i / (EMB / 4);
    int t  = bt % T;
    int b  = bt / T;
    int tok = idx[b * TSRC + t];               // idx rows have stride TSRC (128)
    reinterpret_cast<float4*>(X)[(size_t)bt * (EMB / 4) + e4] =
        reinterpret_cast<const float4*>(emb)[(size_t)tok * (EMB / 4) + e4];
}

// ---------------- generic tiled GEMM: C = A[M,K] @ W[N,K]^T + bias ----------
// mode 0: C[m*N + n]
// mode 1: FC scatter: m -> (b,t), C[((b*TSRC)+t+1)*VOCAB + n]
// mode 2: GI transpose-scatter: m=(b,t), C[(t*G3 + n)*64 + b]  (b-contiguous)
#define GTM 64
#define GTN 64
#define GTK 16
__global__ __launch_bounds__(256) void gemm_bias(
    const float* __restrict__ A, const float* __restrict__ W,
    const float* __restrict__ bias, float* __restrict__ C,
    int M, int N, int K, int mode, int Tdim)
{
    __shared__ __align__(16) float sA[GTK][GTM];
    __shared__ __align__(16) float sB[GTK][GTN];
    int m0 = blockIdx.x * GTM;
    int n0 = blockIdx.y * GTN;
    int tid = threadIdx.x;
    int tx = tid & 15;          // n micro index
    int ty = tid >> 4;          // m micro index
    int lm = tid >> 2;          // 0..63 (row for staging)
    int lk = (tid & 3) * 4;     // 0,4,8,12

    unsigned long long acc2[4][2];
#pragma unroll
    for (int i = 0; i < 4; i++) { acc2[i][0] = 0ull; acc2[i][1] = 0ull; }

    for (int k0 = 0; k0 < K; k0 += GTK) {
        float4 av = *reinterpret_cast<const float4*>(&A[(size_t)(m0 + lm) * K + k0 + lk]);
        float4 bv = make_float4(0.f, 0.f, 0.f, 0.f);
        int wn = n0 + lm;
        if (wn < N)
            bv = *reinterpret_cast<const float4*>(&W[(size_t)wn * K + k0 + lk]);
        __syncthreads();
        sA[lk + 0][lm] = av.x; sA[lk + 1][lm] = av.y;
        sA[lk + 2][lm] = av.z; sA[lk + 3][lm] = av.w;
        sB[lk + 0][lm] = bv.x; sB[lk + 1][lm] = bv.y;
        sB[lk + 2][lm] = bv.z; sB[lk + 3][lm] = bv.w;
        __syncthreads();
#pragma unroll
        for (int k = 0; k < GTK; k++) {
            float a[4];
            *reinterpret_cast<float4*>(a) = *reinterpret_cast<const float4*>(&sA[k][ty * 4]);
            ulonglong2 bp = *reinterpret_cast<const ulonglong2*>(&sB[k][tx * 4]);
#pragma unroll
            for (int i = 0; i < 4; i++) {
                unsigned long long ad = dup2(a[i]);
                fma2(acc2[i][0], ad, bp.x);
                fma2(acc2[i][1], ad, bp.y);
            }
        }
    }

#pragma unroll
    for (int i = 0; i < 4; i++) {
        int m = m0 + ty * 4 + i;
        float accf[4];
        asm("mov.b64 {%0, %1}, %2;" : "=f"(accf[0]), "=f"(accf[1]) : "l"(acc2[i][0]));
        asm("mov.b64 {%0, %1}, %2;" : "=f"(accf[2]), "=f"(accf[3]) : "l"(acc2[i][1]));
        if (mode == 0) {
            size_t rowbase = (size_t)m * N;
#pragma unroll
            for (int j = 0; j < 4; j++) {
                int n = n0 + tx * 4 + j;
                if (n < N) C[rowbase + n] = accf[j] + bias[n];
            }
        } else if (mode == 1) {
            int b = m / TDEC, t = m % TDEC;
            size_t rowbase = ((size_t)b * TSRC + t + 1) * VOCAB;
#pragma unroll
            for (int j = 0; j < 4; j++) {
                int n = n0 + tx * 4 + j;
                if (n < N) C[rowbase + n] = accf[j] + bias[n];
            }
        } else {
            int b = m / Tdim, t = m % Tdim;
#pragma unroll
            for (int j = 0; j < 4; j++) {
                int n = n0 + tx * 4 + j;
                C[((size_t)t * G3 + n) * 64 + b] = accf[j] + bias[n];
            }
        }
    }
}

// ---------------- helpers for persistent GRU --------------------------------
__device__ __forceinline__ void cp_async16(void* smem_dst, const void* gmem_src)
{
    unsigned int saddr = (unsigned int)__cvta_generic_to_shared(smem_dst);
    asm volatile("cp.async.cg.shared.global [%0], [%1], 16;\n"
                 :: "r"(saddr), "l"(gmem_src) : "memory");
}

// lane-0 pure-spin acquire-poll on a chunk flag; warp syncs after.
__device__ __forceinline__ void wait_flag(const unsigned int* p, unsigned int tgt)
{
    if ((threadIdx.x & 31) == 0) {
        unsigned int v;
        do {
            asm volatile("ld.acquire.gpu.global.u32 %0, [%1];" : "=r"(v) : "l"(p));
        } while (v < tgt);
    }
    __syncwarp();
}

// release-increment: orders this block's prior (bar-ordered) stores, no MEMBAR.
__device__ __forceinline__ void release_flag(unsigned int* p)
{
    asm volatile("red.release.gpu.global.add.u32 [%0], %1;" :: "l"(p), "r"(1u) : "memory");
}

// ---------------- persistent GRU layer ---------------------------------------
// Block: 4 columns x 64 batches. Warp w: k-slice [64w, 64w+64); lane = batch
// (2 per thread). w-loads broadcast, h-loads conflict-free (SHROW=516).
// 8-way k-split reduced via smem partials; outputs staged through smem and
// written as coalesced float4 STGs; handoff via ld.acquire / red.release flags.
__global__ __launch_bounds__(NTHR, 1) void gru_layer(
    const float* __restrict__ Whh, const float* __restrict__ bhh,
    const float* __restrict__ GI, int T,
    float* __restrict__ hbuf0, float* __restrict__ hbuf1,
    float* __restrict__ Yout, int layer)
{
    extern __shared__ float smem[];
    float* sW = smem;                       // [12][SWROW]
    float* sH = smem + SW_FLOATS;           // [64][SHROW]
    float* sP = sH + SH_FLOATS;             // [768][12]
    float* sO = sP + SP_FLOATS;             // [64][4]

    const int tid = threadIdx.x;
    const int w   = tid >> 5;               // warp 0..7 = k-slice
    const int l   = tid & 31;               // lane = batch (and batch+32)
    const int bid = blockIdx.x;
    const int c0  = bid * CPB;

    // epilogue role: thread handles (cc, be)
    const int cc  = tid >> 6;               // 0..3
    const int be  = tid & 63;               // 0..63
    const int cg  = c0 + cc;

    unsigned int* myflag = &g_FLAG[layer][bid >> 4];
    const unsigned int* flags = &g_FLAG[layer][0];

    // ---- load Whh slice (12 rows x 512) to smem, once per layer ----
    for (int idx = tid; idx < 12 * (HID / 4); idx += NTHR) {
        int r  = idx >> 7;                  // row = g*4+cc2
        int k4 = idx & 127;
        float4 v = reinterpret_cast<const float4*>(Whh)
                       [(size_t)((r >> 2) * HID + c0 + (r & 3)) * (HID / 4) + k4];
        *reinterpret_cast<float4*>(sW + r * SWROW + k4 * 4) = v;
    }
    const float br = bhh[cg];
    const float bz = bhh[HID + cg];
    const float bn = bhh[2 * HID + cg];
    __syncthreads();

    const float* sWb  = sW + 64 * w;        // this warp's k-slice within w rows
    float* sHr0 = sH + l * SHROW + 64 * w;
    float* sHr1 = sH + (l + 32) * SHROW + 64 * w;

    for (int t = 0; t < T; t++) {
        const float* hin  = (t & 1) ? hbuf1 : hbuf0;
        float*       hout = (t & 1) ? hbuf0 : hbuf1;
        const unsigned int tgt = 16u * (unsigned int)t;

        // ---- per-warp: wait for this k-chunk's producers, stage 16KB ----
        if (t > 0) wait_flag(&flags[w], tgt);
        {
            const float* s0 = hin + l * HID + 64 * w;
            const float* s1 = hin + (l + 32) * HID + 64 * w;
#pragma unroll
            for (int j = 0; j < 16; j++) cp_async16(sHr0 + 4 * j, s0 + 4 * j);
#pragma unroll
            for (int j = 0; j < 16; j++) cp_async16(sHr1 + 4 * j, s1 + 4 * j);
        }
        asm volatile("cp.async.commit_group;\n" ::: "memory");

        // GI loads (coalesced, [t][n][b] layout) — issue early
        const size_t gt = (size_t)t * G3;
        const float ir  = GI[(gt + cg) * 64 + be];
        const float iz  = GI[(gt + HID + cg) * 64 + be];
        const float inn = GI[(gt + 2 * HID + cg) * 64 + be];

        asm volatile("cp.async.wait_group 0;\n" ::: "memory");

        // ---- k-loop over this warp's 64-k slice ----
        unsigned long long acc[12][2];
#pragma unroll
        for (int r = 0; r < 12; r++) { acc[r][0] = 0ull; acc[r][1] = 0ull; }

#pragma unroll 4
        for (int kq = 0; kq < 16; kq++) {
            ulonglong2 H0 = *reinterpret_cast<const ulonglong2*>(sHr0 + 4 * kq);
            ulonglong2 H1 = *reinterpret_cast<const ulonglong2*>(sHr1 + 4 * kq);
#pragma unroll
            for (int r = 0; r < 12; r++) {
                ulonglong2 Wv = *reinterpret_cast<const ulonglong2*>(
                    sWb + r * SWROW + 4 * kq);
                fma2(acc[r][0], Wv.x, H0.x);
                fma2(acc[r][0], Wv.y, H0.y);
                fma2(acc[r][1], Wv.x, H1.x);
                fma2(acc[r][1], Wv.y, H1.y);
            }
        }

        // ---- fold + store partials ----
#pragma unroll
        for (int r = 0; r < 12; r++) {
            sP[(r * 64 + l) * 12 + w]      = sum2(acc[r][0]);
            sP[(r * 64 + l + 32) * 12 + w] = sum2(acc[r][1]);
        }
        __syncthreads();

        // ---- combine (deterministic order) + fused gate epilogue ----
        float gsum[3];
#pragma unroll
        for (int g = 0; g < 3; g++) {
            int o = (g * 4 + cc) * 64 + be;
            float4 pa = *reinterpret_cast<const float4*>(sP + o * 12);
            float4 pb = *reinterpret_cast<const float4*>(sP + o * 12 + 4);
            gsum[g] = ((pa.x + pa.y) + (pa.z + pa.w)) +
                      ((pb.x + pb.y) + (pb.z + pb.w));
        }
        float hprev = sH[be * SHROW + cg];
        float r = 1.0f / (1.0f + expf(-(ir + gsum[0] + br)));
        float z = 1.0f / (1.0f + expf(-(iz + gsum[1] + bz)));
        float n = tanhf(inn + r * (gsum[2] + bn));
        float hv = (1.0f - z) * n + z * hprev;
        sO[be * 4 + cc] = hv;
        __syncthreads();

        // ---- coalesced float4 output writes (one warp pair) ----
        if (tid < BATCH) {
            float4 v = *reinterpret_cast<const float4*>(sO + tid * 4);
            *reinterpret_cast<float4*>(hout + tid * HID + c0) = v;
            *reinterpret_cast<float4*>(Yout + ((size_t)tid * T + t) * HID + c0) = v;
        }
        __syncthreads();

        // ---- release this block's chunk for step t+1 (release-atomic) ----
        if (tid == 0) release_flag(myflag);
    }
}

// ---------------- launch -----------------------------------------------------
extern "C" void kernel_launch(void* const* d_in, const int* in_sizes, int n_in,
                              void* d_out, int out_size)
{
    const int*   src     = (const int*)  d_in[0];
    const int*   trg     = (const int*)  d_in[1];
    const float* enc_emb = (const float*)d_in[2];
    const float* enc_Wih = (const float*)d_in[3];
    const float* enc_Whh = (const float*)d_in[4];
    const float* enc_bih = (const float*)d_in[5];
    const float* enc_bhh = (const float*)d_in[6];
    const float* dec_emb = (const float*)d_in[7];
    const float* dec_Wih = (const float*)d_in[8];
    const float* dec_Whh = (const float*)d_in[9];
    const float* dec_bih = (const float*)d_in[10];
    const float* dec_bhh = (const float*)d_in[11];
    const float* fc_W    = (const float*)d_in[12];
    const float* fc_b    = (const float*)d_in[13];
    float* out = (float*)d_out;

    float *X, *GI, *Y, *H;
    cudaGetSymbolAddress((void**)&X,  g_X);
    cudaGetSymbolAddress((void**)&GI, g_GI);
    cudaGetSymbolAddress((void**)&Y,  g_Y);
    cudaGetSymbolAddress((void**)&H,  g_H);

    cudaFuncSetAttribute(gru_layer, cudaFuncAttributeMaxDynamicSharedMemorySize,
                         GRU_SMEM);

    // zero t=0 output slice + initial hidden states + flags
    init_k<<<(BATCH * VOCAB + 255) / 256, 256>>>(out);

    // ===================== encoder =====================
    embed_k<<<(BATCH * TSRC * (EMB / 4) + 255) / 256, 256>>>(src, enc_emb, X, TSRC);
    for (int l = 0; l < 2; l++) {
        const float* Ain = (l == 0) ? X : Y;
        gemm_bias<<<dim3((BATCH * TSRC) / GTM, G3 / GTN), 256>>>(
            Ain, enc_Wih + (size_t)l * G3 * HID, enc_bih + l * G3,
            GI, BATCH * TSRC, G3, (l == 0) ? EMB : HID, 2, TSRC);
        float* h0 = H + (2 * l + 0) * BATCH * HID;
        float* h1 = H + (2 * l + 1) * BATCH * HID;
        // T=128 (even): final hidden lands in h0 — exactly where decoder reads it.
        gru_layer<<<NBLK, NTHR, GRU_SMEM>>>(
            enc_Whh + (size_t)l * G3 * HID, enc_bhh + l * G3, GI, TSRC, h0, h1, Y, l);
    }

    // ===================== decoder =====================
    embed_k<<<(BATCH * TDEC * (EMB / 4) + 255) / 256, 256>>>(trg, dec_emb, X, TDEC);
    for (int l = 0; l < 2; l++) {
        const float* Ain = (l == 0) ? X : Y;
        gemm_bias<<<dim3((BATCH * TDEC) / GTM, G3 / GTN), 256>>>(
            Ain, dec_Wih + (size_t)l * G3 * HID, dec_bih + l * G3,
            GI, BATCH * TDEC, G3, (l == 0) ? EMB : HID, 2, TDEC);
        float* h0 = H + (2 * l + 0) * BATCH * HID;   // encoder final hidden
        float* h1 = H + (2 * l + 1) * BATCH * HID;
        gru_layer<<<NBLK, NTHR, GRU_SMEM>>>(
            dec_Whh + (size_t)l * G3 * HID, dec_bhh + l * G3, GI, TDEC, h0, h1, Y, 2 + l);
    }

    // ===================== FC head =====================
    gemm_bias<<<dim3((BATCH * TDEC) / GTM, (VOCAB + GTN - 1) / GTN), 256>>>(
        Y, fc_W, fc_b, out, BATCH * TDEC, VOCAB, HID, 1, TDEC);
}

// round 13
// speedup vs baseline: 1.4619x; 1.3614x over previous
#include <cuda_runtime.h>
#include <math.h>

#define BATCH 64
#define EMB   512
#define HID   512
#define G3    1536         // 3*HID
#define VOCAB 10000
#define TSRC  128
#define TDEC  127          // trg[:, :-1]

// ---------------- persistent GRU geometry -----------------------------------
// 128 blocks = 32 col-groups (16 cols) x 4 batch-groups (16 batches).
// Batch-groups are closed sync domains (GRU recurrence independent per batch).
#define RNTHR 256
#define SW_F (48 * 516)               // 3 gates x 16 cols, row stride 516
#define SH_F (16 * 516)               // 16 batches x 512 (+pad)
#define SP_F (768 * 12)               // 48 rows x 16 batches partials, 8 warps + pad
#define SO_F 256                      // 16 x 16 staged outputs
#define GRU_SMEM ((SW_F + SH_F + SP_F + SO_F) * 4)   // 169984 B

// ---------------- scratch (device globals; no allocation allowed) ----------
__device__ float g_X [(size_t)BATCH * TSRC * EMB];   // embedded inputs
__device__ float g_GI[(size_t)BATCH * TSRC * G3];    // input proj, layout [t][n][b]
__device__ float g_Y [(size_t)BATCH * TSRC * HID];   // layer outputs
__device__ float g_H [4 * BATCH * HID];              // ping-pong hidden (2 layers x 2)
__device__ unsigned int g_FLAG[4][8];                // per-layer, per-batch-group counters

// ---------------- f32x2 packed-FMA helpers ----------------------------------
__device__ __forceinline__ void fma2(unsigned long long& d,
                                     unsigned long long a, unsigned long long b)
{
    asm("fma.rn.f32x2 %0, %1, %2, %0;" : "+l"(d) : "l"(a), "l"(b));
}
__device__ __forceinline__ float sum2(unsigned long long p)
{
    float lo, hi;
    asm("mov.b64 {%0, %1}, %2;" : "=f"(lo), "=f"(hi) : "l"(p));
    return lo + hi;
}
__device__ __forceinline__ unsigned long long dup2(float a)
{
    unsigned long long r;
    asm("mov.b64 %0, {%1, %1};" : "=l"(r) : "f"(a));
    return r;
}

// ---------------- init: zero out[t=0] slice + hidden + flags ----------------
__global__ void init_k(float* __restrict__ out)
{
    int i = blockIdx.x * blockDim.x + threadIdx.x;
    if (i < BATCH * VOCAB) {
        int b = i / VOCAB, v = i % VOCAB;
        out[((size_t)b * TSRC) * VOCAB + v] = 0.0f;
    }
    if (i < 4 * BATCH * HID) g_H[i] = 0.0f;
    if (i < 32) (&g_FLAG[0][0])[i] = 0u;
}

// ---------------- embedding gather (float4) ---------------------------------
__global__ void embed_k(const int* __restrict__ idx, const float* __restrict__ emb,
                        float* __restrict__ X, int T)
{
    int i = blockIdx.x * blockDim.x + threadIdx.x;
    int total = BATCH * T * (EMB / 4);
    if (i >= total) return;
    int e4 = i % (EMB / 4);
    int bt = i / (EMB / 4);
    int t  = bt % T;
    int b  = bt / T;
    int tok = idx[b * TSRC + t];               // idx rows have stride TSRC (128)
    reinterpret_cast<float4*>(X)[(size_t)bt * (EMB / 4) + e4] =
        reinterpret_cast<const float4*>(emb)[(size_t)tok * (EMB / 4) + e4];
}

// ---------------- 128x128 tiled GEMM: C = A[M,K] @ W[N,K]^T + bias ----------
// 8x8 register blocking per thread (FMA-bound, ~4 cyc/output).
// mode 1: FC scatter: m -> (b,t), C[((b*TSRC)+t+1)*VOCAB + n]
// mode 2: GI transpose-scatter: m=(b,t), C[(t*G3 + n)*64 + b]  (b-contiguous)
// A rows are always within the allocated scratch (8192 rows) -> unguarded loads.
#define TM 128
#define TN 128
#define TK 8
__global__ __launch_bounds__(256) void gemm_bias(
    const float* __restrict__ A, const float* __restrict__ W,
    const float* __restrict__ bias, float* __restrict__ C,
    int M, int N, int K, int mode, int Tdim)
{
    __shared__ __align__(16) float sA[TK][TM];
    __shared__ __align__(16) float sB[TK][TN];
    const int m0 = blockIdx.x * TM;
    const int n0 = blockIdx.y * TN;
    const int tid = threadIdx.x;
    const int tx = tid & 15;       // n micro (8 cols)
    const int ty = tid >> 4;       // m micro (8 rows)
    const int lrow = tid >> 1;     // 0..127 staging row
    const int lk4  = (tid & 1) * 4;

    unsigned long long acc[8][4];
#pragma unroll
    for (int i = 0; i < 8; i++)
#pragma unroll
        for (int p = 0; p < 4; p++) acc[i][p] = 0ull;

    const int niter = K / TK;
    float4 avr = *reinterpret_cast<const float4*>(&A[(size_t)(m0 + lrow) * K + lk4]);
    float4 bvr = make_float4(0.f, 0.f, 0.f, 0.f);
    if (n0 + lrow < N)
        bvr = *reinterpret_cast<const float4*>(&W[(size_t)(n0 + lrow) * K + lk4]);

    for (int it = 0; it < niter; it++) {
        __syncthreads();
        sA[lk4 + 0][lrow] = avr.x; sA[lk4 + 1][lrow] = avr.y;
        sA[lk4 + 2][lrow] = avr.z; sA[lk4 + 3][lrow] = avr.w;
        sB[lk4 + 0][lrow] = bvr.x; sB[lk4 + 1][lrow] = bvr.y;
        sB[lk4 + 2][lrow] = bvr.z; sB[lk4 + 3][lrow] = bvr.w;
        __syncthreads();
        if (it + 1 < niter) {
            int k0 = (it + 1) * TK;
            avr = *reinterpret_cast<const float4*>(&A[(size_t)(m0 + lrow) * K + k0 + lk4]);
            if (n0 + lrow < N)
                bvr = *reinterpret_cast<const float4*>(&W[(size_t)(n0 + lrow) * K + k0 + lk4]);
        }
#pragma unroll
        for (int k = 0; k < TK; k++) {
            float a[8];
            *reinterpret_cast<float4*>(a)     = *reinterpret_cast<const float4*>(&sA[k][ty * 8]);
            *reinterpret_cast<float4*>(a + 4) = *reinterpret_cast<const float4*>(&sA[k][ty * 8 + 4]);
            ulonglong2 b01 = *reinterpret_cast<const ulonglong2*>(&sB[k][tx * 8]);
            ulonglong2 b23 = *reinterpret_cast<const ulonglong2*>(&sB[k][tx * 8 + 4]);
#pragma unroll
            for (int i = 0; i < 8; i++) {
                unsigned long long ad = dup2(a[i]);
                fma2(acc[i][0], ad, b01.x);
                fma2(acc[i][1], ad, b01.y);
                fma2(acc[i][2], ad, b23.x);
                fma2(acc[i][3], ad, b23.y);
            }
        }
    }

    // bias (shared across the 8 m-rows)
    float bs[8];
#pragma unroll
    for (int j = 0; j < 8; j++) {
        int n = n0 + tx * 8 + j;
        bs[j] = (n < N) ? bias[n] : 0.0f;
    }

#pragma unroll
    for (int i = 0; i < 8; i++) {
        int m = m0 + ty * 8 + i;
        if (m >= M) continue;
        float c[8];
#pragma unroll
        for (int p = 0; p < 4; p++) {
            asm("mov.b64 {%0, %1}, %2;" : "=f"(c[2 * p]), "=f"(c[2 * p + 1]) : "l"(acc[i][p]));
        }
        if (mode == 1) {
            int b = m / TDEC, t = m % TDEC;
            float* row = C + ((size_t)b * TSRC + t + 1) * VOCAB;
#pragma unroll
            for (int jp = 0; jp < 8; jp += 4) {
                int n = n0 + tx * 8 + jp;
                if (n + 3 < N) {
                    float4 v = make_float4(c[jp] + bs[jp], c[jp + 1] + bs[jp + 1],
                                           c[jp + 2] + bs[jp + 2], c[jp + 3] + bs[jp + 3]);
                    *reinterpret_cast<float4*>(row + n) = v;
                }
            }
        } else {
            int b = m / Tdim, t = m % Tdim;
#pragma unroll
            for (int j = 0; j < 8; j++) {
                int n = n0 + tx * 8 + j;
                C[((size_t)t * G3 + n) * 64 + b] = c[j] + bs[j];
            }
        }
    }
}

// ---------------- helpers for persistent GRU --------------------------------
__device__ __forceinline__ void cp_async16(void* smem_dst, const void* gmem_src)
{
    unsigned int saddr = (unsigned int)__cvta_generic_to_shared(smem_dst);
    asm volatile("cp.async.cg.shared.global [%0], [%1], 16;\n"
                 :: "r"(saddr), "l"(gmem_src) : "memory");
}

__device__ __forceinline__ void wait_flag(const unsigned int* p, unsigned int tgt)
{
    if ((threadIdx.x & 31) == 0) {
        unsigned int v;
        do {
            asm volatile("ld.acquire.gpu.global.u32 %0, [%1];" : "=r"(v) : "l"(p));
        } while (v < tgt);
    }
    __syncwarp();
}

__device__ __forceinline__ void release_flag(unsigned int* p)
{
    asm volatile("red.release.gpu.global.add.u32 [%0], %1;" :: "l"(p), "r"(1u) : "memory");
}

// ---------------- persistent GRU layer (2D split) ----------------------------
// Block (bc=bid>>2, bb=bid&3): 16 cols x 16 batches. Only h[bb-group] (32 KB)
// is staged per step; sync domain = the 32 blocks sharing bb (closed group).
// Warp w = k-slice [64w,64w+64); lane: rh=l>>4 picks 24 of 48 gate-rows,
// bat=l&15 picks batch. Weight LDS are 2-way broadcast; 8-way k-split reduced
// via smem partials; fused gate epilogue; coalesced float4 output writes.
__global__ __launch_bounds__(RNTHR, 1) void gru_layer(
    const float* __restrict__ Whh, const float* __restrict__ bhh,
    const float* __restrict__ GI, int T,
    float* __restrict__ hbuf0, float* __restrict__ hbuf1,
    float* __restrict__ Yout, int layer)
{
    extern __shared__ float smem[];
    float* sW = smem;                 // [48][516]
    float* sH = sW + SW_F;            // [16][516]
    float* sP = sH + SH_F;            // [768][12]
    float* sO = sP + SP_F;            // [16][16]

    const int tid = threadIdx.x;
    const int bid = blockIdx.x;
    const int bb  = bid & 3;          // batch-group
    const int bc  = bid >> 2;         // col-group
    const int c0  = bc * 16;
    const int b0  = bb * 16;

    const int w   = tid >> 5;         // warp = k-slice
    const int l   = tid & 31;
    const int rh  = l >> 4;           // row half (24 rows each)
    const int bat16 = l & 15;         // batch within group (k-loop role)

    // epilogue role
    const int cc  = tid >> 4;         // 0..15 col within group
    const int bat = tid & 15;         // 0..15 batch within group
    const int cg  = c0 + cc;

    unsigned int* myflag = &g_FLAG[layer][bb];

    // ---- load Whh slice (48 rows x 512) into smem, once per layer ----
    for (int idx = tid; idx < 48 * (HID / 4); idx += RNTHR) {
        int r  = idx >> 7;            // 0..47 = g*16 + col
        int k4 = idx & 127;
        float4 v = reinterpret_cast<const float4*>(Whh)
                       [(size_t)((r >> 4) * HID + c0 + (r & 15)) * (HID / 4) + k4];
        *reinterpret_cast<float4*>(sW + r * 516 + k4 * 4) = v;
    }
    const float br = bhh[cg];
    const float bz = bhh[HID + cg];
    const float bn = bhh[2 * HID + cg];
    __syncthreads();

    const float* sWb = sW + (rh * 24) * 516 + w * 64;
    const float* sHb = sH + bat16 * 516 + w * 64;

    for (int t = 0; t < T; t++) {
        const float* hin  = (t & 1) ? hbuf1 : hbuf0;
        float*       hout = (t & 1) ? hbuf0 : hbuf1;

        // ---- wait for this batch-group's producers (32 blocks) ----
        if (t > 0) wait_flag(myflag, 32u * (unsigned int)t);

        // ---- stage h[bb-group][k-slice w]: 4 KB per warp ----
#pragma unroll
        for (int j = 0; j < 8; j++) {
            int idx = l + 32 * j;         // 0..255
            int row = idx >> 4;           // 0..15
            int k4  = idx & 15;           // 0..15
            cp_async16(sH + row * 516 + w * 64 + k4 * 4,
                       hin + (size_t)(b0 + row) * HID + w * 64 + k4 * 4);
        }
        asm volatile("cp.async.commit_group;\n" ::: "memory");

        // GI prefetch (coalesced: b contiguous), consumed in epilogue
        const size_t gt = (size_t)t * G3;
        const float ir  = GI[(gt + cg) * 64 + b0 + bat];
        const float iz  = GI[(gt + HID + cg) * 64 + b0 + bat];
        const float inn = GI[(gt + 2 * HID + cg) * 64 + b0 + bat];

        asm volatile("cp.async.wait_group 0;\n" ::: "memory");
        __syncthreads();

        // ---- k-loop: 24 rows x 64 k per thread ----
        unsigned long long acc[24];
#pragma unroll
        for (int j = 0; j < 24; j++) acc[j] = 0ull;

#pragma unroll 4
        for (int kq = 0; kq < 16; kq++) {
            ulonglong2 hp = *reinterpret_cast<const ulonglong2*>(sHb + kq * 4);
#pragma unroll
            for (int j = 0; j < 24; j++) {
                ulonglong2 wv = *reinterpret_cast<const ulonglong2*>(
                    sWb + j * 516 + kq * 4);
                fma2(acc[j], wv.x, hp.x);
                fma2(acc[j], wv.y, hp.y);
            }
        }

        // ---- store k-split partials ----
#pragma unroll
        for (int j = 0; j < 24; j++) {
            int rr = rh * 24 + j;
            sP[(rr * 16 + bat16) * 12 + w] = sum2(acc[j]);
        }
        __syncthreads();

        // ---- combine (deterministic) + fused gate epilogue ----
        float gsum[3];
#pragma unroll
        for (int g = 0; g < 3; g++) {
            int o = ((g * 16 + cc) * 16 + bat) * 12;
            float4 pa = *reinterpret_cast<const float4*>(sP + o);
            float4 pb = *reinterpret_cast<const float4*>(sP + o + 4);
            gsum[g] = ((pa.x + pa.y) + (pa.z + pa.w)) +
                      ((pb.x + pb.y) + (pb.z + pb.w));
        }
        float hprev = sH[bat * 516 + cg];
        float r = 1.0f / (1.0f + expf(-(ir + gsum[0] + br)));
        float z = 1.0f / (1.0f + expf(-(iz + gsum[1] + bz)));
        float n = tanhf(inn + r * (gsum[2] + bn));
        float hv = (1.0f - z) * n + z * hprev;
        sO[bat * 16 + cc] = hv;
        __syncthreads();

        // ---- coalesced float4 output writes (64 threads) ----
        if (tid < 64) {
            int batch = tid >> 2;
            int c4 = (tid & 3) * 4;
            float4 v = *reinterpret_cast<const float4*>(sO + batch * 16 + c4);
            *reinterpret_cast<float4*>(hout + (size_t)(b0 + batch) * HID + c0 + c4) = v;
            *reinterpret_cast<float4*>(
                Yout + ((size_t)(b0 + batch) * T + t) * HID + c0 + c4) = v;
        }
        __syncthreads();

        // ---- release (publishes bar-ordered writes at gpu scope) ----
        if (tid == 0) release_flag(myflag);
    }
}

// ---------------- launch -----------------------------------------------------
extern "C" void kernel_launch(void* const* d_in, const int* in_sizes, int n_in,
                              void* d_out, int out_size)
{
    const int*   src     = (const int*)  d_in[0];
    const int*   trg     = (const int*)  d_in[1];
    const float* enc_emb = (const float*)d_in[2];
    const float* enc_Wih = (const float*)d_in[3];
    const float* enc_Whh = (const float*)d_in[4];
    const float* enc_bih = (const float*)d_in[5];
    const float* enc_bhh = (const float*)d_in[6];
    const float* dec_emb = (const float*)d_in[7];
    const float* dec_Wih = (const float*)d_in[8];
    const float* dec_Whh = (const float*)d_in[9];
    const float* dec_bih = (const float*)d_in[10];
    const float* dec_bhh = (const float*)d_in[11];
    const float* fc_W    = (const float*)d_in[12];
    const float* fc_b    = (const float*)d_in[13];
    float* out = (float*)d_out;

    float *X, *GI, *Y, *H;
    cudaGetSymbolAddress((void**)&X,  g_X);
    cudaGetSymbolAddress((void**)&GI, g_GI);
    cudaGetSymbolAddress((void**)&Y,  g_Y);
    cudaGetSymbolAddress((void**)&H,  g_H);

    cudaFuncSetAttribute(gru_layer, cudaFuncAttributeMaxDynamicSharedMemorySize,
                         GRU_SMEM);

    // zero t=0 output slice + initial hidden states + flags
    init_k<<<(BATCH * VOCAB + 255) / 256, 256>>>(out);

    // ===================== encoder =====================
    embed_k<<<(BATCH * TSRC * (EMB / 4) + 255) / 256, 256>>>(src, enc_emb, X, TSRC);
    for (int l = 0; l < 2; l++) {
        const float* Ain = (l == 0) ? X : Y;
        gemm_bias<<<dim3(64, G3 / TN), 256>>>(
            Ain, enc_Wih + (size_t)l * G3 * HID, enc_bih + l * G3,
            GI, BATCH * TSRC, G3, 512, 2, TSRC);
        float* h0 = H + (2 * l + 0) * BATCH * HID;
        float* h1 = H + (2 * l + 1) * BATCH * HID;
        // T=128 (even): final hidden lands in h0 — where the decoder reads it.
        gru_layer<<<128, RNTHR, GRU_SMEM>>>(
            enc_Whh + (size_t)l * G3 * HID, enc_bhh + l * G3, GI, TSRC, h0, h1, Y, l);
    }

    // ===================== decoder =====================
    embed_k<<<(BATCH * TDEC * (EMB / 4) + 255) / 256, 256>>>(trg, dec_emb, X, TDEC);
    for (int l = 0; l < 2; l++) {
        const float* Ain = (l == 0) ? X : Y;
        gemm_bias<<<dim3(64, G3 / TN), 256>>>(
            Ain, dec_Wih + (size_t)l * G3 * HID, dec_bih + l * G3,
            GI, BATCH * TDEC, G3, 512, 2, TDEC);
        float* h0 = H + (2 * l + 0) * BATCH * HID;   // encoder final hidden
        float* h1 = H + (2 * l + 1) * BATCH * HID;
        gru_layer<<<128, RNTHR, GRU_SMEM>>>(
            dec_Whh + (size_t)l * G3 * HID, dec_bhh + l * G3, GI, TDEC, h0, h1, Y, 2 + l);
    }

    // ===================== FC head =====================
    gemm_bias<<<dim3(64, (VOCAB + TN - 1) / TN), 256>>>(
        Y, fc_W, fc_b, out, BATCH * TDEC, VOCAB, 512, 1, TDEC);
}